// round 13
// baseline (speedup 1.0000x reference)
#include <cuda_runtime.h>
#include <cuda_fp16.h>
#include <cstdint>

// GPTQ 4-bit: pre-dequant to fp16 scratch, then warp-specialized HMMA GEMM.
// Pass 1: xh = fp16(x)                 [M,K]  (64 MB)
// Pass 2: wt = fp16(s*(w4-(z4+1)))^T   [N,K]  (90 MB)
// Pass 3: out = xh @ wt^T, mma.sync m16n8k16, fp32 accum.
// R13: ILP over TLP. 8 consumer warps (64x64 warp tile, 2/SMSP) + 2 producer
//      warps = 320 threads (reg cap 204). Two fragment sets per warp; chunk
//      body software-pipelined LDSM(next) under MMA(cur) so smem crossbar and
//      tensor pipe overlap instead of convoying.

#define M_DIM 8192
#define N_DIM 11008
#define K_DIM 4096
#define BM 256
#define BN 128
#define BK 32
#define CHUNKS (K_DIM / BK)          // 128
#define ROWB 80                      // 32 halves (64B) + 16B pad per smem row
#define A_BYTES (BM * ROWB)          // 20480
#define B_BYTES (BN * ROWB)          // 10240
#define STAGEB (A_BYTES + B_BYTES)   // 30720
#define STAGES 7
#define MBAR_BASE (STAGES * STAGEB)          // 215040
#define SMEM_TOTAL (MBAR_BASE + 128)         // 215168
#define CONSUMERS 256                         // warps 0-7
#define PRODUCERS 64                          // warps 8-9
#define THREADS (CONSUMERS + PRODUCERS)       // 320

__device__ __half g_xh[(size_t)M_DIM * K_DIM];   // 64 MB scratch
__device__ __half g_wt[(size_t)N_DIM * K_DIM];   // 90 MB scratch

__device__ __forceinline__ uint32_t smem_u32(const void* p) {
    uint32_t a;
    asm("{ .reg .u64 t; cvta.to.shared.u64 t, %1; cvt.u32.u64 %0, t; }"
        : "=r"(a) : "l"(p));
    return a;
}

#define LDMX4(r, addr)                                                       \
    asm volatile("ldmatrix.sync.aligned.m8n8.x4.shared.b16 {%0,%1,%2,%3}, [%4];" \
        : "=r"((r)[0]), "=r"((r)[1]), "=r"((r)[2]), "=r"((r)[3]) : "r"(addr))

#define MMA16816(d, a, b0, b1)                                               \
    asm volatile("mma.sync.aligned.m16n8k16.row.col.f32.f16.f16.f32 "        \
        "{%0,%1,%2,%3}, {%4,%5,%6,%7}, {%8,%9}, {%0,%1,%2,%3};"              \
        : "+f"((d)[0]), "+f"((d)[1]), "+f"((d)[2]), "+f"((d)[3])             \
        : "r"((a)[0]), "r"((a)[1]), "r"((a)[2]), "r"((a)[3]), "r"(b0), "r"(b1))

#define CP16(dst, src)                                                       \
    asm volatile("cp.async.cg.shared.global [%0], [%1], 16;"                 \
        :: "r"(dst), "l"(src) : "memory")

#define CP_MBAR_ARRIVE(mbar)                                                 \
    asm volatile("cp.async.mbarrier.arrive.noinc.shared.b64 [%0];"           \
        :: "r"(mbar) : "memory")

#define MBAR_INIT(addr, cnt) \
    asm volatile("mbarrier.init.shared.b64 [%0], %1;" :: "r"(addr), "r"(cnt) : "memory")
#define MBAR_ARRIVE(addr) \
    asm volatile("mbarrier.arrive.shared.b64 _, [%0];" :: "r"(addr) : "memory")

#define MBAR_WAIT(addr, parity) do {                                              \
    uint32_t _m = (addr), _p = (parity), _d;                                      \
    asm volatile("{\n\t.reg .pred p;\n\t"                                         \
        "mbarrier.try_wait.parity.shared.b64 p, [%1], %2, 0x989680;\n\t"          \
        "selp.b32 %0, 1, 0, p;\n\t}" : "=r"(_d) : "r"(_m), "r"(_p) : "memory");   \
    if (!_d) {                                                                    \
        asm volatile("{\n\t.reg .pred P1;\n\t"                                    \
            "W_%=:\n\t"                                                           \
            "mbarrier.try_wait.parity.shared.b64 P1, [%0], %1, 0x989680;\n\t"     \
            "@P1 bra.uni D_%=;\n\t"                                               \
            "bra.uni W_%=;\n\t"                                                   \
            "D_%=:\n\t}" :: "r"(_m), "r"(_p) : "memory");                         \
    }                                                                             \
} while (0)

__device__ __forceinline__ uint32_t pack2(float a, float b) {
    __half2 h = __float22half2_rn(make_float2(a, b));
    return *reinterpret_cast<uint32_t*>(&h);
}

// ---------- pass 1: x fp32 -> fp16 ----------
__global__ __launch_bounds__(256) void cvt_x_kernel(const float* __restrict__ x) {
    const size_t i = ((size_t)blockIdx.x * 256 + threadIdx.x) * 8;
    const float4 a = *reinterpret_cast<const float4*>(x + i);
    const float4 b = *reinterpret_cast<const float4*>(x + i + 4);
    uint4 o;
    o.x = pack2(a.x, a.y); o.y = pack2(a.z, a.w);
    o.z = pack2(b.x, b.y); o.w = pack2(b.z, b.w);
    *reinterpret_cast<uint4*>(g_xh + i) = o;
}

// ---------- pass 2: dequant to W^T fp16 [N,K] ----------
__global__ __launch_bounds__(256) void dequant_kernel(const int* __restrict__ qweight,
                                                      const float* __restrict__ scales,
                                                      const int* __restrict__ qzeros) {
    const int n  = blockIdx.x * 256 + threadIdx.x;     // 0..11007
    const int kw = blockIdx.y;                          // 0..511 (k-word)
    const int g  = kw >> 4;                             // group = (kw*8)/128
    const float s = scales[(size_t)g * N_DIM + n];
    const unsigned qz = (unsigned)qzeros[(size_t)g * (N_DIM / 8) + (n >> 3)];
    const float neg = -s * (float)(((qz >> ((n & 7) * 4)) & 0xFu) + 1u);
    const unsigned q = (unsigned)qweight[(size_t)kw * N_DIM + n];
    uint4 o;
    uint32_t* p = &o.x;
    #pragma unroll
    for (int j = 0; j < 4; j++) {
        const float f0 = fmaf(s, (float)((q >> (8 * j))     & 0xFu), neg);
        const float f1 = fmaf(s, (float)((q >> (8 * j + 4)) & 0xFu), neg);
        p[j] = pack2(f0, f1);
    }
    *reinterpret_cast<uint4*>(g_wt + (size_t)n * K_DIM + kw * 8) = o;
}

// ---------- nop: pads launch order so ncu (captures index 3) hits the GEMM ----------
__global__ void nop_kernel() {}

// ---------- pass 3: warp-specialized HMMA GEMM ----------
__global__ __launch_bounds__(THREADS, 1)
void hgemm_main(float* __restrict__ out)
{
    extern __shared__ __align__(16) char smem[];
    const uint32_t sb = smem_u32(smem);
    const int tid  = threadIdx.x;
    const int lane = tid & 31;
    const int wid  = tid >> 5;
    const int m0   = blockIdx.x * BM;
    const int n0   = blockIdx.y * BN;

    const uint32_t fullB  = sb + MBAR_BASE;        // count=PRODUCERS (async arrivals)
    const uint32_t emptyB = sb + MBAR_BASE + 64;   // count=8 (one per consumer warp)
    if (tid == 0) {
        #pragma unroll
        for (int s = 0; s < STAGES; s++) {
            MBAR_INIT(fullB  + s * 8, PRODUCERS);
            MBAR_INIT(emptyB + s * 8, 8);
        }
    }
    __syncthreads();

    if (wid >= 8) {
        // ================= PRODUCERS (warps 8-9, 64 threads) =================
        const int p = tid - CONSUMERS;   // 0..63
        const __half* aSrcP = g_xh + (size_t)(m0 + 4 * p) * K_DIM;
        const __half* bSrcP = g_wt + (size_t)(n0 + 2 * p) * K_DIM;
        const uint32_t aDstP = sb + (uint32_t)(4 * p) * ROWB;
        const uint32_t bDstP = sb + (uint32_t)A_BYTES + (uint32_t)(2 * p) * ROWB;

        int s = 0, ep = 1;
        #pragma unroll 1
        for (int c = 0; c < CHUNKS; c++) {
            if (c >= STAGES) MBAR_WAIT(emptyB + s * 8, ep);
            const uint32_t base = (uint32_t)(s * STAGEB);
            const int koff = c * BK;
            #pragma unroll
            for (int i = 0; i < 4; i++) {
                const __half* src = aSrcP + (size_t)i * K_DIM + koff;
                const uint32_t dst = aDstP + base + i * ROWB;
                CP16(dst,      src);
                CP16(dst + 16, src + 8);
                CP16(dst + 32, src + 16);
                CP16(dst + 48, src + 24);
            }
            #pragma unroll
            for (int i = 0; i < 2; i++) {
                const __half* src = bSrcP + (size_t)i * K_DIM + koff;
                const uint32_t dst = bDstP + base + i * ROWB;
                CP16(dst,      src);
                CP16(dst + 16, src + 8);
                CP16(dst + 32, src + 16);
                CP16(dst + 48, src + 24);
            }
            CP_MBAR_ARRIVE(fullB + s * 8);
            if (++s == STAGES) { s = 0; ep ^= 1; }
        }
        return;
    }

    // ================= CONSUMERS (warps 0-7, warp tile 64x64) =================
    const int wm = wid & 3;          // 0..3 (M)
    const int wn = wid >> 2;         // 0..1 (N)
    const int lr  = lane & 15;
    const int lsB = (lane >> 4) * 16;
    const uint32_t aLd0 = sb + (uint32_t)((wm * 64 + lr) * ROWB) + lsB;
    const uint32_t bLd0 = sb + (uint32_t)(A_BYTES + (wn * 64 + lr) * ROWB) + lsB;

    float acc[4][8][4];
    #pragma unroll
    for (int i = 0; i < 4; i++)
        #pragma unroll
        for (int j = 0; j < 8; j++)
            #pragma unroll
            for (int e = 0; e < 4; e++) acc[i][j][e] = 0.0f;

    uint32_t aF[2][4][4];   // [set][mi][frag]
    uint32_t bF[2][4][4];   // [set][nj][frag]

    // preload set0 = (chunk 0, ks0)
    MBAR_WAIT(fullB, 0);
    #pragma unroll
    for (int mi = 0; mi < 4; mi++) LDMX4(aF[0][mi], aLd0 + mi * 16 * ROWB);
    #pragma unroll
    for (int nj = 0; nj < 4; nj++) LDMX4(bF[0][nj], bLd0 + nj * 16 * ROWB);

    int s = 0, fp = 0;
    #pragma unroll 1
    for (int c = 0; c < CHUNKS; c++) {
        const uint32_t aLd = aLd0 + (uint32_t)(s * STAGEB);
        const uint32_t bLd = bLd0 + (uint32_t)(s * STAGEB);

        // LDSM set1 <- (c, ks1): overlaps MMA(set0) below
        #pragma unroll
        for (int mi = 0; mi < 4; mi++) LDMX4(aF[1][mi], aLd + 32 + mi * 16 * ROWB);
        #pragma unroll
        for (int nj = 0; nj < 4; nj++) LDMX4(bF[1][nj], bLd + 32 + nj * 16 * ROWB);

        // MMA set0
        #pragma unroll
        for (int nj = 0; nj < 4; nj++)
            #pragma unroll
            for (int mi = 0; mi < 4; mi++) {
                MMA16816(acc[mi][2 * nj],     aF[0][mi], bF[0][nj][0], bF[0][nj][2]);
                MMA16816(acc[mi][2 * nj + 1], aF[0][mi], bF[0][nj][1], bF[0][nj][3]);
            }

        // advance ring; prefetch set0 <- (c+1, ks0): overlaps MMA(set1) below
        const int sn = (s + 1 == STAGES) ? 0 : s + 1;
        const int fpn = (s + 1 == STAGES) ? (fp ^ 1) : fp;
        if (c + 1 < CHUNKS) {
            MBAR_WAIT(fullB + sn * 8, fpn);
            const uint32_t aLdN = aLd0 + (uint32_t)(sn * STAGEB);
            const uint32_t bLdN = bLd0 + (uint32_t)(sn * STAGEB);
            #pragma unroll
            for (int mi = 0; mi < 4; mi++) LDMX4(aF[0][mi], aLdN + mi * 16 * ROWB);
            #pragma unroll
            for (int nj = 0; nj < 4; nj++) LDMX4(bF[0][nj], bLdN + nj * 16 * ROWB);
        }

        // MMA set1
        #pragma unroll
        for (int nj = 0; nj < 4; nj++)
            #pragma unroll
            for (int mi = 0; mi < 4; mi++) {
                MMA16816(acc[mi][2 * nj],     aF[1][mi], bF[1][nj][0], bF[1][nj][2]);
                MMA16816(acc[mi][2 * nj + 1], aF[1][mi], bF[1][nj][1], bF[1][nj][3]);
            }

        // stage s fully read -> recycle (one arrive per warp, count=8)
        if (lane == 0) MBAR_ARRIVE(emptyB + s * 8);
        s = sn; fp = fpn;
    }

    // epilogue
    #pragma unroll
    for (int mi = 0; mi < 4; mi++) {
        const int row = m0 + wm * 64 + mi * 16 + (lane >> 2);
        float* o0 = out + (size_t)row * N_DIM + n0 + wn * 64 + (lane & 3) * 2;
        float* o1 = o0 + (size_t)8 * N_DIM;
        #pragma unroll
        for (int j = 0; j < 8; j++) {
            *(float2*)(o0 + j * 8) = make_float2(acc[mi][j][0], acc[mi][j][1]);
            *(float2*)(o1 + j * 8) = make_float2(acc[mi][j][2], acc[mi][j][3]);
        }
    }
}

extern "C" void kernel_launch(void* const* d_in, const int* in_sizes, int n_in,
                              void* d_out, int out_size)
{
    const float* x       = (const float*)d_in[0];
    const int*   qweight = (const int*)  d_in[1];
    const float* scales  = (const float*)d_in[2];
    const int*   qzeros  = (const int*)  d_in[3];
    float* out = (float*)d_out;

    static bool attr_set = false;
    if (!attr_set) {
        cudaFuncSetAttribute(hgemm_main,
                             cudaFuncAttributeMaxDynamicSharedMemorySize, SMEM_TOTAL);
        attr_set = true;
    }

    cvt_x_kernel<<<(int)((size_t)M_DIM * K_DIM / 8 / 256), 256>>>(x);       // idx 0
    dequant_kernel<<<dim3(N_DIM / 256, K_DIM / 8), 256>>>(qweight, scales, qzeros); // idx 1
    nop_kernel<<<1, 32>>>();                                                // idx 2

    dim3 grid(M_DIM / BM, N_DIM / BN);   // (32, 86), m-fastest for L2 locality
    hgemm_main<<<grid, THREADS, SMEM_TOTAL>>>(out);                         // idx 3 -> ncu
}

// round 14
// speedup vs baseline: 2.0929x; 2.0929x over previous
#include <cuda_runtime.h>
#include <cuda_fp16.h>
#include <cstdint>

// GPTQ 4-bit: pre-dequant to fp16 scratch, then warp-specialized HMMA GEMM.
// Pass 1: xh = fp16(x)                 [M,K]  (64 MB)
// Pass 2: wt = fp16(s*(w4-(z4+1)))^T   [N,K]  (90 MB)
// Pass 3: out = xh @ wt^T, mma.sync m16n8k16, fp32 accum.
// R14: 2 warp-specialized CTAs per SM. Each CTA: 8 consumer warps (32x64 warp
//      tile) + 1 producer warp, 5-stage mbarrier ring. The two CTAs' phases
//      are uncorrelated, so one CTA's MMA phase covers the other's LDSM phase
//      (convoy-breaking without fragment double-buffering).

#define M_DIM 8192
#define N_DIM 11008
#define K_DIM 4096
#define BM 128
#define BN 128
#define BK 32
#define CHUNKS (K_DIM / BK)          // 128
#define ROWB 80                      // 32 halves (64B) + 16B pad per smem row
#define A_BYTES (BM * ROWB)          // 10240
#define B_BYTES (BN * ROWB)          // 10240
#define STAGEB (A_BYTES + B_BYTES)   // 20480
#define STAGES 5
#define MBAR_BASE (STAGES * STAGEB)          // 102400
#define SMEM_TOTAL (MBAR_BASE + 128)         // 102528 (x2 CTAs ~ 205 KB/SM)
#define CONSUMERS 256                         // warps 0-7
#define PRODUCERS 32                          // warp 8
#define THREADS (CONSUMERS + PRODUCERS)       // 288

__device__ __half g_xh[(size_t)M_DIM * K_DIM];   // 64 MB scratch
__device__ __half g_wt[(size_t)N_DIM * K_DIM];   // 90 MB scratch

__device__ __forceinline__ uint32_t smem_u32(const void* p) {
    uint32_t a;
    asm("{ .reg .u64 t; cvta.to.shared.u64 t, %1; cvt.u32.u64 %0, t; }"
        : "=r"(a) : "l"(p));
    return a;
}

#define LDMX4(r, addr)                                                       \
    asm volatile("ldmatrix.sync.aligned.m8n8.x4.shared.b16 {%0,%1,%2,%3}, [%4];" \
        : "=r"((r)[0]), "=r"((r)[1]), "=r"((r)[2]), "=r"((r)[3]) : "r"(addr))

#define MMA16816(d, a, b0, b1)                                               \
    asm volatile("mma.sync.aligned.m16n8k16.row.col.f32.f16.f16.f32 "        \
        "{%0,%1,%2,%3}, {%4,%5,%6,%7}, {%8,%9}, {%0,%1,%2,%3};"              \
        : "+f"((d)[0]), "+f"((d)[1]), "+f"((d)[2]), "+f"((d)[3])             \
        : "r"((a)[0]), "r"((a)[1]), "r"((a)[2]), "r"((a)[3]), "r"(b0), "r"(b1))

#define CP16(dst, src)                                                       \
    asm volatile("cp.async.cg.shared.global [%0], [%1], 16;"                 \
        :: "r"(dst), "l"(src) : "memory")

#define CP_MBAR_ARRIVE(mbar)                                                 \
    asm volatile("cp.async.mbarrier.arrive.noinc.shared.b64 [%0];"           \
        :: "r"(mbar) : "memory")

#define MBAR_INIT(addr, cnt) \
    asm volatile("mbarrier.init.shared.b64 [%0], %1;" :: "r"(addr), "r"(cnt) : "memory")
#define MBAR_ARRIVE(addr) \
    asm volatile("mbarrier.arrive.shared.b64 _, [%0];" :: "r"(addr) : "memory")

#define MBAR_WAIT(addr, parity) do {                                              \
    uint32_t _m = (addr), _p = (parity), _d;                                      \
    asm volatile("{\n\t.reg .pred p;\n\t"                                         \
        "mbarrier.try_wait.parity.shared.b64 p, [%1], %2, 0x989680;\n\t"          \
        "selp.b32 %0, 1, 0, p;\n\t}" : "=r"(_d) : "r"(_m), "r"(_p) : "memory");   \
    if (!_d) {                                                                    \
        asm volatile("{\n\t.reg .pred P1;\n\t"                                    \
            "W_%=:\n\t"                                                           \
            "mbarrier.try_wait.parity.shared.b64 P1, [%0], %1, 0x989680;\n\t"     \
            "@P1 bra.uni D_%=;\n\t"                                               \
            "bra.uni W_%=;\n\t"                                                   \
            "D_%=:\n\t}" :: "r"(_m), "r"(_p) : "memory");                         \
    }                                                                             \
} while (0)

__device__ __forceinline__ uint32_t pack2(float a, float b) {
    __half2 h = __float22half2_rn(make_float2(a, b));
    return *reinterpret_cast<uint32_t*>(&h);
}

// ---------- pass 1: x fp32 -> fp16 ----------
__global__ __launch_bounds__(256) void cvt_x_kernel(const float* __restrict__ x) {
    const size_t i = ((size_t)blockIdx.x * 256 + threadIdx.x) * 8;
    const float4 a = *reinterpret_cast<const float4*>(x + i);
    const float4 b = *reinterpret_cast<const float4*>(x + i + 4);
    uint4 o;
    o.x = pack2(a.x, a.y); o.y = pack2(a.z, a.w);
    o.z = pack2(b.x, b.y); o.w = pack2(b.z, b.w);
    *reinterpret_cast<uint4*>(g_xh + i) = o;
}

// ---------- pass 2: dequant to W^T fp16 [N,K] ----------
__global__ __launch_bounds__(256) void dequant_kernel(const int* __restrict__ qweight,
                                                      const float* __restrict__ scales,
                                                      const int* __restrict__ qzeros) {
    const int n  = blockIdx.x * 256 + threadIdx.x;     // 0..11007
    const int kw = blockIdx.y;                          // 0..511 (k-word)
    const int g  = kw >> 4;                             // group = (kw*8)/128
    const float s = scales[(size_t)g * N_DIM + n];
    const unsigned qz = (unsigned)qzeros[(size_t)g * (N_DIM / 8) + (n >> 3)];
    const float neg = -s * (float)(((qz >> ((n & 7) * 4)) & 0xFu) + 1u);
    const unsigned q = (unsigned)qweight[(size_t)kw * N_DIM + n];
    uint4 o;
    uint32_t* p = &o.x;
    #pragma unroll
    for (int j = 0; j < 4; j++) {
        const float f0 = fmaf(s, (float)((q >> (8 * j))     & 0xFu), neg);
        const float f1 = fmaf(s, (float)((q >> (8 * j + 4)) & 0xFu), neg);
        p[j] = pack2(f0, f1);
    }
    *reinterpret_cast<uint4*>(g_wt + (size_t)n * K_DIM + kw * 8) = o;
}

// ---------- nop: pads launch order so ncu (captures index 3) hits the GEMM ----------
__global__ void nop_kernel() {}

// ---------- pass 3: warp-specialized HMMA GEMM, 2 CTAs/SM ----------
__global__ __launch_bounds__(THREADS, 2)
void hgemm_main(float* __restrict__ out)
{
    extern __shared__ __align__(16) char smem[];
    const uint32_t sb = smem_u32(smem);
    const int tid  = threadIdx.x;
    const int lane = tid & 31;
    const int wid  = tid >> 5;
    const int m0   = blockIdx.x * BM;
    const int n0   = blockIdx.y * BN;

    const uint32_t fullB  = sb + MBAR_BASE;        // count=PRODUCERS (async arrivals)
    const uint32_t emptyB = sb + MBAR_BASE + 64;   // count=8 (one per consumer warp)
    if (tid == 0) {
        #pragma unroll
        for (int s = 0; s < STAGES; s++) {
            MBAR_INIT(fullB  + s * 8, PRODUCERS);
            MBAR_INIT(emptyB + s * 8, 8);
        }
    }
    __syncthreads();

    if (wid == 8) {
        // ================= PRODUCER (warp 8, 32 threads) =================
        const int p = lane;   // 0..31; A rows 4p..4p+3, B rows 4p..4p+3
        const __half* aSrcP = g_xh + (size_t)(m0 + 4 * p) * K_DIM;
        const __half* bSrcP = g_wt + (size_t)(n0 + 4 * p) * K_DIM;
        const uint32_t aDstP = sb + (uint32_t)(4 * p) * ROWB;
        const uint32_t bDstP = sb + (uint32_t)A_BYTES + (uint32_t)(4 * p) * ROWB;

        int s = 0, ep = 1;
        #pragma unroll 1
        for (int c = 0; c < CHUNKS; c++) {
            if (c >= STAGES) MBAR_WAIT(emptyB + s * 8, ep);
            const uint32_t base = (uint32_t)(s * STAGEB);
            const int koff = c * BK;
            #pragma unroll
            for (int i = 0; i < 4; i++) {
                const __half* srcA = aSrcP + (size_t)i * K_DIM + koff;
                const uint32_t dstA = aDstP + base + i * ROWB;
                CP16(dstA,      srcA);
                CP16(dstA + 16, srcA + 8);
                CP16(dstA + 32, srcA + 16);
                CP16(dstA + 48, srcA + 24);
                const __half* srcB = bSrcP + (size_t)i * K_DIM + koff;
                const uint32_t dstB = bDstP + base + i * ROWB;
                CP16(dstB,      srcB);
                CP16(dstB + 16, srcB + 8);
                CP16(dstB + 32, srcB + 16);
                CP16(dstB + 48, srcB + 24);
            }
            CP_MBAR_ARRIVE(fullB + s * 8);
            if (++s == STAGES) { s = 0; ep ^= 1; }
        }
        return;
    }

    // ================= CONSUMERS (warps 0-7, warp tile 32x64) =================
    const int wm = wid & 3;          // 0..3 (M, 32-row blocks)
    const int wn = wid >> 2;         // 0..1 (N, 64-col blocks)
    const int lr  = lane & 15;
    const int lsB = (lane >> 4) * 16;
    const uint32_t aLd0 = sb + (uint32_t)((wm * 32 + lr) * ROWB) + lsB;
    const uint32_t bLd0 = sb + (uint32_t)(A_BYTES + (wn * 64 + lr) * ROWB) + lsB;

    float acc[2][8][4];
    #pragma unroll
    for (int i = 0; i < 2; i++)
        #pragma unroll
        for (int j = 0; j < 8; j++)
            #pragma unroll
            for (int e = 0; e < 4; e++) acc[i][j][e] = 0.0f;

    int s = 0, fp = 0;
    #pragma unroll 1
    for (int c = 0; c < CHUNKS; c++) {
        MBAR_WAIT(fullB + s * 8, fp);
        const uint32_t aLd = aLd0 + (uint32_t)(s * STAGEB);
        const uint32_t bLd = bLd0 + (uint32_t)(s * STAGEB);

        #pragma unroll
        for (int ks = 0; ks < 2; ks++) {
            uint32_t a[2][4], b[4][4];
            #pragma unroll
            for (int mi = 0; mi < 2; mi++)
                LDMX4(a[mi], aLd + ks * 32 + mi * 16 * ROWB);
            #pragma unroll
            for (int nj = 0; nj < 4; nj++)
                LDMX4(b[nj], bLd + ks * 32 + nj * 16 * ROWB);
            #pragma unroll
            for (int nj = 0; nj < 4; nj++)
                #pragma unroll
                for (int mi = 0; mi < 2; mi++) {
                    MMA16816(acc[mi][2 * nj],     a[mi], b[nj][0], b[nj][2]);
                    MMA16816(acc[mi][2 * nj + 1], a[mi], b[nj][1], b[nj][3]);
                }
        }

        if (lane == 0) MBAR_ARRIVE(emptyB + s * 8);
        if (++s == STAGES) { s = 0; fp ^= 1; }
    }

    // epilogue
    #pragma unroll
    for (int mi = 0; mi < 2; mi++) {
        const int row = m0 + wm * 32 + mi * 16 + (lane >> 2);
        float* o0 = out + (size_t)row * N_DIM + n0 + wn * 64 + (lane & 3) * 2;
        float* o1 = o0 + (size_t)8 * N_DIM;
        #pragma unroll
        for (int j = 0; j < 8; j++) {
            *(float2*)(o0 + j * 8) = make_float2(acc[mi][j][0], acc[mi][j][1]);
            *(float2*)(o1 + j * 8) = make_float2(acc[mi][j][2], acc[mi][j][3]);
        }
    }
}

extern "C" void kernel_launch(void* const* d_in, const int* in_sizes, int n_in,
                              void* d_out, int out_size)
{
    const float* x       = (const float*)d_in[0];
    const int*   qweight = (const int*)  d_in[1];
    const float* scales  = (const float*)d_in[2];
    const int*   qzeros  = (const int*)  d_in[3];
    float* out = (float*)d_out;

    static bool attr_set = false;
    if (!attr_set) {
        cudaFuncSetAttribute(hgemm_main,
                             cudaFuncAttributeMaxDynamicSharedMemorySize, SMEM_TOTAL);
        attr_set = true;
    }

    cvt_x_kernel<<<(int)((size_t)M_DIM * K_DIM / 8 / 256), 256>>>(x);       // idx 0
    dequant_kernel<<<dim3(N_DIM / 256, K_DIM / 8), 256>>>(qweight, scales, qzeros); // idx 1
    nop_kernel<<<1, 32>>>();                                                // idx 2

    dim3 grid(M_DIM / BM, N_DIM / BN);   // (64, 86), m-fastest for L2 locality
    hgemm_main<<<grid, THREADS, SMEM_TOTAL>>>(out);                         // idx 3 -> ncu
}

// round 15
// speedup vs baseline: 2.6621x; 1.2720x over previous
#include <cuda_runtime.h>
#include <cuda_fp16.h>
#include <cstdint>

// GPTQ 4-bit: pre-dequant to fp16 scratch, then cp.async-pipelined HMMA GEMM.
// Pass 1: xh = fp16(x)                 [M,K]  (64 MB)
// Pass 2: wt = fp16(s*(w4-(z4+1)))^T   [N,K]  (90 MB)
// Pass 3: out = xh @ wt^T, mma.sync m16n8k16, fp32 accum.
// R15: 8 warps/SMSP. 2 CTAs x 512 threads per SM (1024 thr = full 64K regfile
//      at 64 regs/thread). CTA tile 128x128, warp tile 32x32 (acc 32 regs).
//      R5-style flat cp.async pipeline, 5 stages. Theory: tensor% has scaled
//      with warps/SMSP (2->18.9%, 4->41%) across all sync schemes; 8 should
//      break the 41% ceiling.

#define M_DIM 8192
#define N_DIM 11008
#define K_DIM 4096
#define BM 128
#define BN 128
#define BK 32
#define CHUNKS (K_DIM / BK)          // 128
#define ROWB 80                      // 32 halves (64B) + 16B pad per smem row
#define A_BYTES (BM * ROWB)          // 10240
#define B_BYTES (BN * ROWB)          // 10240
#define STAGEB (A_BYTES + B_BYTES)   // 20480
#define STAGES 5
#define SMEM_TOTAL (STAGES * STAGEB) // 102400 per CTA (x2 = 204800 per SM)
#define THREADS 512

__device__ __half g_xh[(size_t)M_DIM * K_DIM];   // 64 MB scratch
__device__ __half g_wt[(size_t)N_DIM * K_DIM];   // 90 MB scratch

__device__ __forceinline__ uint32_t smem_u32(const void* p) {
    uint32_t a;
    asm("{ .reg .u64 t; cvta.to.shared.u64 t, %1; cvt.u32.u64 %0, t; }"
        : "=r"(a) : "l"(p));
    return a;
}

#define LDMX4(r, addr)                                                       \
    asm volatile("ldmatrix.sync.aligned.m8n8.x4.shared.b16 {%0,%1,%2,%3}, [%4];" \
        : "=r"((r)[0]), "=r"((r)[1]), "=r"((r)[2]), "=r"((r)[3]) : "r"(addr))

#define MMA16816(d, a, b0, b1)                                               \
    asm volatile("mma.sync.aligned.m16n8k16.row.col.f32.f16.f16.f32 "        \
        "{%0,%1,%2,%3}, {%4,%5,%6,%7}, {%8,%9}, {%0,%1,%2,%3};"              \
        : "+f"((d)[0]), "+f"((d)[1]), "+f"((d)[2]), "+f"((d)[3])             \
        : "r"((a)[0]), "r"((a)[1]), "r"((a)[2]), "r"((a)[3]), "r"(b0), "r"(b1))

#define CP16(dst, src)                                                       \
    asm volatile("cp.async.cg.shared.global [%0], [%1], 16;"                 \
        :: "r"(dst), "l"(src) : "memory")
#define CP_COMMIT() asm volatile("cp.async.commit_group;" ::: "memory")
#define CP_WAIT3()  asm volatile("cp.async.wait_group 3;" ::: "memory")
#define CP_WAIT0()  asm volatile("cp.async.wait_group 0;" ::: "memory")

__device__ __forceinline__ uint32_t pack2(float a, float b) {
    __half2 h = __float22half2_rn(make_float2(a, b));
    return *reinterpret_cast<uint32_t*>(&h);
}

// ---------- pass 1: x fp32 -> fp16 ----------
__global__ __launch_bounds__(256) void cvt_x_kernel(const float* __restrict__ x) {
    const size_t i = ((size_t)blockIdx.x * 256 + threadIdx.x) * 8;
    const float4 a = *reinterpret_cast<const float4*>(x + i);
    const float4 b = *reinterpret_cast<const float4*>(x + i + 4);
    uint4 o;
    o.x = pack2(a.x, a.y); o.y = pack2(a.z, a.w);
    o.z = pack2(b.x, b.y); o.w = pack2(b.z, b.w);
    *reinterpret_cast<uint4*>(g_xh + i) = o;
}

// ---------- pass 2: dequant to W^T fp16 [N,K] ----------
__global__ __launch_bounds__(256) void dequant_kernel(const int* __restrict__ qweight,
                                                      const float* __restrict__ scales,
                                                      const int* __restrict__ qzeros) {
    const int n  = blockIdx.x * 256 + threadIdx.x;     // 0..11007
    const int kw = blockIdx.y;                          // 0..511 (k-word)
    const int g  = kw >> 4;                             // group = (kw*8)/128
    const float s = scales[(size_t)g * N_DIM + n];
    const unsigned qz = (unsigned)qzeros[(size_t)g * (N_DIM / 8) + (n >> 3)];
    const float neg = -s * (float)(((qz >> ((n & 7) * 4)) & 0xFu) + 1u);
    const unsigned q = (unsigned)qweight[(size_t)kw * N_DIM + n];
    uint4 o;
    uint32_t* p = &o.x;
    #pragma unroll
    for (int j = 0; j < 4; j++) {
        const float f0 = fmaf(s, (float)((q >> (8 * j))     & 0xFu), neg);
        const float f1 = fmaf(s, (float)((q >> (8 * j + 4)) & 0xFu), neg);
        p[j] = pack2(f0, f1);
    }
    *reinterpret_cast<uint4*>(g_wt + (size_t)n * K_DIM + kw * 8) = o;
}

// ---------- nop: pads launch order so ncu (captures index 3) hits the GEMM ----------
__global__ void nop_kernel() {}

// ---------- pass 3: HMMA GEMM, 2 CTAs/SM, 8 warps/SMSP ----------
__global__ __launch_bounds__(THREADS, 2)
void hgemm_main(float* __restrict__ out)
{
    extern __shared__ __align__(16) char smem[];
    const uint32_t sb = smem_u32(smem);
    const int tid  = threadIdx.x;
    const int lane = tid & 31;
    const int wid  = tid >> 5;
    const int m0   = blockIdx.x * BM;
    const int n0   = blockIdx.y * BN;

    // producer addressing: A tile 128x64B = 512 x 16B txns, one per thread;
    // same for B. Each thread: 1 A-cp + 1 B-cp per chunk.
    const __half* aSrc0 = g_xh + (size_t)(m0 + (tid >> 2)) * K_DIM + (tid & 3) * 8;
    const uint32_t aDst0 = sb + (uint32_t)((tid >> 2) * ROWB + (tid & 3) * 16);
    const __half* bSrc0 = g_wt + (size_t)(n0 + (tid >> 2)) * K_DIM + (tid & 3) * 8;
    const uint32_t bDst0 = sb + (uint32_t)(A_BYTES + (tid >> 2) * ROWB + (tid & 3) * 16);

    // consumer addressing: 4m x 4n warps, warp tile 32x32
    const int wm = wid & 3;
    const int wn = wid >> 2;
    const int lr  = lane & 15;
    const int lsB = (lane >> 4) * 16;
    const uint32_t aLd0 = sb + (uint32_t)((wm * 32 + lr) * ROWB) + lsB;
    const uint32_t bLd0 = sb + (uint32_t)(A_BYTES + (wn * 32 + lr) * ROWB) + lsB;

    float acc[2][4][4];
    #pragma unroll
    for (int i = 0; i < 2; i++)
        #pragma unroll
        for (int j = 0; j < 4; j++)
            #pragma unroll
            for (int e = 0; e < 4; e++) acc[i][j][e] = 0.0f;

    auto issue = [&](int s, int c) {
        const uint32_t base = (uint32_t)(s * STAGEB);
        CP16(aDst0 + base, aSrc0 + c * BK);
        CP16(bDst0 + base, bSrc0 + c * BK);
    };

    // prologue: chunks 0..3 -> stages 0..3
    issue(0, 0); CP_COMMIT();
    issue(1, 1); CP_COMMIT();
    issue(2, 2); CP_COMMIT();
    issue(3, 3); CP_COMMIT();

    int cs = 0;   // compute stage
    int is = 4;   // issue stage
    #pragma unroll 1
    for (int c = 0; c < CHUNKS; c++) {
        CP_WAIT3();                       // chunk c resident
        __syncthreads();                  // all warps past compute(c-1)
        if (c + 4 < CHUNKS) issue(is, c + 4);
        CP_COMMIT();
        if (++is == STAGES) is = 0;

        const uint32_t aLd = aLd0 + (uint32_t)(cs * STAGEB);
        const uint32_t bLd = bLd0 + (uint32_t)(cs * STAGEB);
        if (++cs == STAGES) cs = 0;

        #pragma unroll
        for (int ks = 0; ks < 2; ks++) {
            uint32_t a[2][4], b[2][4];
            LDMX4(a[0], aLd + ks * 32);
            LDMX4(a[1], aLd + ks * 32 + 16 * ROWB);
            LDMX4(b[0], bLd + ks * 32);
            LDMX4(b[1], bLd + ks * 32 + 16 * ROWB);
            #pragma unroll
            for (int nj = 0; nj < 2; nj++)
                #pragma unroll
                for (int mi = 0; mi < 2; mi++) {
                    MMA16816(acc[mi][2 * nj],     a[mi], b[nj][0], b[nj][2]);
                    MMA16816(acc[mi][2 * nj + 1], a[mi], b[nj][1], b[nj][3]);
                }
        }
    }
    CP_WAIT0();

    // epilogue
    #pragma unroll
    for (int mi = 0; mi < 2; mi++) {
        const int row = m0 + wm * 32 + mi * 16 + (lane >> 2);
        float* o0 = out + (size_t)row * N_DIM + n0 + wn * 32 + (lane & 3) * 2;
        float* o1 = o0 + (size_t)8 * N_DIM;
        #pragma unroll
        for (int j = 0; j < 4; j++) {
            *(float2*)(o0 + j * 8) = make_float2(acc[mi][j][0], acc[mi][j][1]);
            *(float2*)(o1 + j * 8) = make_float2(acc[mi][j][2], acc[mi][j][3]);
        }
    }
}

extern "C" void kernel_launch(void* const* d_in, const int* in_sizes, int n_in,
                              void* d_out, int out_size)
{
    const float* x       = (const float*)d_in[0];
    const int*   qweight = (const int*)  d_in[1];
    const float* scales  = (const float*)d_in[2];
    const int*   qzeros  = (const int*)  d_in[3];
    float* out = (float*)d_out;

    static bool attr_set = false;
    if (!attr_set) {
        cudaFuncSetAttribute(hgemm_main,
                             cudaFuncAttributeMaxDynamicSharedMemorySize, SMEM_TOTAL);
        attr_set = true;
    }

    cvt_x_kernel<<<(int)((size_t)M_DIM * K_DIM / 8 / 256), 256>>>(x);       // idx 0
    dequant_kernel<<<dim3(N_DIM / 256, K_DIM / 8), 256>>>(qweight, scales, qzeros); // idx 1
    nop_kernel<<<1, 32>>>();                                                // idx 2

    dim3 grid(M_DIM / BM, N_DIM / BN);   // (64, 86), m-fastest for L2 locality
    hgemm_main<<<grid, THREADS, SMEM_TOTAL>>>(out);                         // idx 3 -> ncu
}

// round 16
// speedup vs baseline: 3.0838x; 1.1584x over previous
#include <cuda_runtime.h>
#include <cuda_fp16.h>
#include <cstdint>

// GPTQ 4-bit: pre-dequant to fp16 scratch, then cp.async-pipelined HMMA GEMM.
// Pass 1: xh = fp16(x)                 [M,K]  (64 MB)
// Pass 2: wt = fp16(s*(w4-(z4+1)))^T   [N,K]  (90 MB)
// Pass 3: out = xh @ wt^T, mma.sync m16n8k16, fp32 accum.
// R16: 8 warps/SMSP (R15's win) + halved syncs. One 1024-thread CTA per SM,
//      tile 128x256, warp 32x32 (4m x 8n), 7-stage ring (215 KB), sync every
//      2 chunks. Fragment window stays 16 regs so the pair-unrolled body fits
//      the 64-reg cap.

#define M_DIM 8192
#define N_DIM 11008
#define K_DIM 4096
#define BM 128
#define BN 256
#define BK 32
#define CHUNKS (K_DIM / BK)          // 128
#define ROWB 80                      // 32 halves (64B) + 16B pad per smem row
#define A_BYTES (BM * ROWB)          // 10240
#define B_BYTES (BN * ROWB)          // 20480
#define STAGEB (A_BYTES + B_BYTES)   // 30720
#define STAGES 7
#define SMEM_TOTAL (STAGES * STAGEB) // 215040
#define THREADS 1024

__device__ __half g_xh[(size_t)M_DIM * K_DIM];   // 64 MB scratch
__device__ __half g_wt[(size_t)N_DIM * K_DIM];   // 90 MB scratch

__device__ __forceinline__ uint32_t smem_u32(const void* p) {
    uint32_t a;
    asm("{ .reg .u64 t; cvta.to.shared.u64 t, %1; cvt.u32.u64 %0, t; }"
        : "=r"(a) : "l"(p));
    return a;
}

#define LDMX4(r, addr)                                                       \
    asm volatile("ldmatrix.sync.aligned.m8n8.x4.shared.b16 {%0,%1,%2,%3}, [%4];" \
        : "=r"((r)[0]), "=r"((r)[1]), "=r"((r)[2]), "=r"((r)[3]) : "r"(addr))

#define MMA16816(d, a, b0, b1)                                               \
    asm volatile("mma.sync.aligned.m16n8k16.row.col.f32.f16.f16.f32 "        \
        "{%0,%1,%2,%3}, {%4,%5,%6,%7}, {%8,%9}, {%0,%1,%2,%3};"              \
        : "+f"((d)[0]), "+f"((d)[1]), "+f"((d)[2]), "+f"((d)[3])             \
        : "r"((a)[0]), "r"((a)[1]), "r"((a)[2]), "r"((a)[3]), "r"(b0), "r"(b1))

#define CP16(dst, src)                                                       \
    asm volatile("cp.async.cg.shared.global [%0], [%1], 16;"                 \
        :: "r"(dst), "l"(src) : "memory")
#define CP_COMMIT() asm volatile("cp.async.commit_group;" ::: "memory")
#define CP_WAIT2()  asm volatile("cp.async.wait_group 2;" ::: "memory")
#define CP_WAIT0()  asm volatile("cp.async.wait_group 0;" ::: "memory")

__device__ __forceinline__ uint32_t pack2(float a, float b) {
    __half2 h = __float22half2_rn(make_float2(a, b));
    return *reinterpret_cast<uint32_t*>(&h);
}

// ---------- pass 1: x fp32 -> fp16 ----------
__global__ __launch_bounds__(256) void cvt_x_kernel(const float* __restrict__ x) {
    const size_t i = ((size_t)blockIdx.x * 256 + threadIdx.x) * 8;
    const float4 a = *reinterpret_cast<const float4*>(x + i);
    const float4 b = *reinterpret_cast<const float4*>(x + i + 4);
    uint4 o;
    o.x = pack2(a.x, a.y); o.y = pack2(a.z, a.w);
    o.z = pack2(b.x, b.y); o.w = pack2(b.z, b.w);
    *reinterpret_cast<uint4*>(g_xh + i) = o;
}

// ---------- pass 2: dequant to W^T fp16 [N,K] ----------
__global__ __launch_bounds__(256) void dequant_kernel(const int* __restrict__ qweight,
                                                      const float* __restrict__ scales,
                                                      const int* __restrict__ qzeros) {
    const int n  = blockIdx.x * 256 + threadIdx.x;     // 0..11007
    const int kw = blockIdx.y;                          // 0..511 (k-word)
    const int g  = kw >> 4;                             // group = (kw*8)/128
    const float s = scales[(size_t)g * N_DIM + n];
    const unsigned qz = (unsigned)qzeros[(size_t)g * (N_DIM / 8) + (n >> 3)];
    const float neg = -s * (float)(((qz >> ((n & 7) * 4)) & 0xFu) + 1u);
    const unsigned q = (unsigned)qweight[(size_t)kw * N_DIM + n];
    uint4 o;
    uint32_t* p = &o.x;
    #pragma unroll
    for (int j = 0; j < 4; j++) {
        const float f0 = fmaf(s, (float)((q >> (8 * j))     & 0xFu), neg);
        const float f1 = fmaf(s, (float)((q >> (8 * j + 4)) & 0xFu), neg);
        p[j] = pack2(f0, f1);
    }
    *reinterpret_cast<uint4*>(g_wt + (size_t)n * K_DIM + kw * 8) = o;
}

// ---------- nop: pads launch order so ncu (captures index 3) hits the GEMM ----------
__global__ void nop_kernel() {}

// ---------- pass 3: HMMA GEMM, 1024-thread CTA, pair-synced 7-stage ring ----------
__global__ __launch_bounds__(THREADS, 1)
void hgemm_main(float* __restrict__ out)
{
    extern __shared__ __align__(16) char smem[];
    const uint32_t sb = smem_u32(smem);
    const int tid  = threadIdx.x;
    const int lane = tid & 31;
    const int wid  = tid >> 5;
    const int m0   = blockIdx.x * BM;
    const int n0   = blockIdx.y * BN;

    // producer addressing: B 256 rows x 4 segs = 1024 txns (1/thread);
    // A 128 rows x 4 segs = 512 txns (threads 0-511, warp-uniform split).
    const int brow = tid >> 2, bseg = tid & 3;
    const __half* bSrc0 = g_wt + (size_t)(n0 + brow) * K_DIM + bseg * 8;
    const uint32_t bDst0 = sb + (uint32_t)(A_BYTES + brow * ROWB + bseg * 16);
    const int arow = (tid & 511) >> 2, aseg = tid & 3;
    const __half* aSrc0 = g_xh + (size_t)(m0 + arow) * K_DIM + aseg * 8;
    const uint32_t aDst0 = sb + (uint32_t)(arow * ROWB + aseg * 16);
    const bool doA = (tid < 512);

    // consumer addressing: 4m x 8n warps, warp tile 32x32
    const int wm = wid & 3;
    const int wn = wid >> 2;          // 0..7
    const int lr  = lane & 15;
    const int lsB = (lane >> 4) * 16;
    const uint32_t aLd0 = sb + (uint32_t)((wm * 32 + lr) * ROWB) + lsB;
    const uint32_t bLd0 = sb + (uint32_t)(A_BYTES + (wn * 32 + lr) * ROWB) + lsB;

    float acc[2][4][4];
    #pragma unroll
    for (int i = 0; i < 2; i++)
        #pragma unroll
        for (int j = 0; j < 4; j++)
            #pragma unroll
            for (int e = 0; e < 4; e++) acc[i][j][e] = 0.0f;

    auto issue = [&](int s, int c) {
        const uint32_t base = (uint32_t)(s * STAGEB);
        CP16(bDst0 + base, bSrc0 + c * BK);
        if (doA) CP16(aDst0 + base, aSrc0 + c * BK);
    };

    auto compute_ks = [&](uint32_t aLd, uint32_t bLd) {
        uint32_t a[2][4], b[2][4];
        LDMX4(a[0], aLd);
        LDMX4(a[1], aLd + 16 * ROWB);
        LDMX4(b[0], bLd);
        LDMX4(b[1], bLd + 16 * ROWB);
        #pragma unroll
        for (int nj = 0; nj < 2; nj++)
            #pragma unroll
            for (int mi = 0; mi < 2; mi++) {
                MMA16816(acc[mi][2 * nj],     a[mi], b[nj][0], b[nj][2]);
                MMA16816(acc[mi][2 * nj + 1], a[mi], b[nj][1], b[nj][3]);
            }
    };

    // prologue: chunks 0..3 -> stages 0..3 (4 commit groups)
    issue(0, 0); CP_COMMIT();
    issue(1, 1); CP_COMMIT();
    issue(2, 2); CP_COMMIT();
    issue(3, 3); CP_COMMIT();

    int cs = 0;   // stage of chunk c
    int is = 4;   // stage for next issue
    #pragma unroll 1
    for (int c = 0; c < CHUNKS; c += 2) {
        CP_WAIT2();                       // chunks c, c+1 resident
        __syncthreads();                  // all warps done through chunk c-1

        const int cs1 = (cs + 1 == STAGES) ? 0 : cs + 1;
        const uint32_t aLdA = aLd0 + (uint32_t)(cs  * STAGEB);
        const uint32_t bLdA = bLd0 + (uint32_t)(cs  * STAGEB);
        const uint32_t aLdB = aLd0 + (uint32_t)(cs1 * STAGEB);
        const uint32_t bLdB = bLd0 + (uint32_t)(cs1 * STAGEB);

        // chunk c, ks0 (LDSM first so post-sync smem reads start immediately)
        compute_ks(aLdA, bLdA);
        if (c + 4 < CHUNKS) issue(is, c + 4);
        CP_COMMIT();
        if (++is == STAGES) is = 0;
        // chunk c, ks1
        compute_ks(aLdA + 32, bLdA + 32);
        if (c + 5 < CHUNKS) issue(is, c + 5);
        CP_COMMIT();
        if (++is == STAGES) is = 0;
        // chunk c+1
        compute_ks(aLdB, bLdB);
        compute_ks(aLdB + 32, bLdB + 32);

        cs = (cs1 + 1 == STAGES) ? 0 : cs1 + 1;
    }
    CP_WAIT0();

    // epilogue
    #pragma unroll
    for (int mi = 0; mi < 2; mi++) {
        const int row = m0 + wm * 32 + mi * 16 + (lane >> 2);
        float* o0 = out + (size_t)row * N_DIM + n0 + wn * 32 + (lane & 3) * 2;
        float* o1 = o0 + (size_t)8 * N_DIM;
        #pragma unroll
        for (int j = 0; j < 4; j++) {
            *(float2*)(o0 + j * 8) = make_float2(acc[mi][j][0], acc[mi][j][1]);
            *(float2*)(o1 + j * 8) = make_float2(acc[mi][j][2], acc[mi][j][3]);
        }
    }
}

extern "C" void kernel_launch(void* const* d_in, const int* in_sizes, int n_in,
                              void* d_out, int out_size)
{
    const float* x       = (const float*)d_in[0];
    const int*   qweight = (const int*)  d_in[1];
    const float* scales  = (const float*)d_in[2];
    const int*   qzeros  = (const int*)  d_in[3];
    float* out = (float*)d_out;

    static bool attr_set = false;
    if (!attr_set) {
        cudaFuncSetAttribute(hgemm_main,
                             cudaFuncAttributeMaxDynamicSharedMemorySize, SMEM_TOTAL);
        attr_set = true;
    }

    cvt_x_kernel<<<(int)((size_t)M_DIM * K_DIM / 8 / 256), 256>>>(x);       // idx 0
    dequant_kernel<<<dim3(N_DIM / 256, K_DIM / 8), 256>>>(qweight, scales, qzeros); // idx 1
    nop_kernel<<<1, 32>>>();                                                // idx 2

    dim3 grid(M_DIM / BM, N_DIM / BN);   // (64, 43), m-fastest for L2 locality
    hgemm_main<<<grid, THREADS, SMEM_TOTAL>>>(out);                         // idx 3 -> ncu
}